// round 6
// baseline (speedup 1.0000x reference)
#include <cuda_runtime.h>
#include <cuda_bf16.h>
#include <cstdint>

// ---------------------------------------------------------------------------
// AttentionPool: B=8, N=4096, DIM=1536, H=24, hd=64, R=8
// out[b,r,:] = softmax_n( q_r . k_n  masked ) @ v @ Wp^T + bp
// Reformulated (8x FLOP cut: K/V projections pushed through the einsums):
//   x8   = x[:, :8]                                  [64,1536]
//   q    = (x8 @ Wq^T) * SCALE                       [64,1536]   (row=(b,r), col=(h,d))
//   qk[b,h*8+r,c] = sum_d q[(b,r),(h,d)] * Wk[(h,d),c]   [8,192,1536]
//   logits[b,g,n] = sum_c qk[b,g,c] * x[b,n,c]           [8,192,4096]  (tf32 MMA)
//   p = masked softmax over n
//   y[b,g,c] = sum_n p[b,g,n] * x[b,n,c]                 [8,192,1536]  (tf32 MMA)
//   xcls[(b,r),(h,d)] = sum_c y[b,h*8+r,c] * Wv[(h,d),c] [64,1536]
//   out = xcls @ Wp^T + bp                               [64,1536]
// ---------------------------------------------------------------------------

#define DIMC   1536
#define NTOK   4096
#define NB     8
#define NH     24
#define HD     64
#define RR     8
#define NG     192          // NH*RR
#define SCALE  0.125f       // 64^-0.5
#define MASKW  4088         // NTOK - RR

// ------------------------- scratch (static device memory) ------------------
__device__ float g_x8[64 * DIMC];
__device__ float g_q[64 * DIMC];
__device__ float g_part[6 * 64 * DIMC];          // split-K partials (reused)
__device__ float g_qk[NB * NG * DIMC];
__device__ float g_p[NB * NG * NTOK];            // logits -> probs (in place)
__device__ float g_y[NB * NG * DIMC];
__device__ float g_xcls[64 * DIMC];
__device__ int   g_maskmode;                     // 0=int32, 1=byte, 2=float32

// ------------------------- helpers -----------------------------------------
__device__ __forceinline__ uint32_t f2tf32(float f) {
    uint32_t u;
    asm("cvt.rna.tf32.f32 %0, %1;" : "=r"(u) : "f"(f));
    return u;
}

__device__ __forceinline__ void mma_tf32(float* c, const uint32_t* a, const uint32_t* b) {
    asm volatile(
        "mma.sync.aligned.m16n8k8.row.col.f32.tf32.tf32.f32 "
        "{%0,%1,%2,%3}, {%4,%5,%6,%7}, {%8,%9}, {%0,%1,%2,%3};"
        : "+f"(c[0]), "+f"(c[1]), "+f"(c[2]), "+f"(c[3])
        : "r"(a[0]), "r"(a[1]), "r"(a[2]), "r"(a[3]),
          "r"(b[0]), "r"(b[1]));
}

// ------------------------- mask dtype detection -----------------------------
__global__ void detect_mask_kernel(const unsigned int* __restrict__ m) {
    __shared__ int s_f, s_nb;
    if (threadIdx.x == 0) { s_f = 0; s_nb = 0; }
    __syncthreads();
    unsigned int w = m[threadIdx.x];            // first 128 words (512B, safe)
    if (w == 0x3F800000u) atomicOr(&s_f, 1);
    else if (w > 1u)      atomicOr(&s_nb, 1);
    __syncthreads();
    if (threadIdx.x == 0) g_maskmode = s_f ? 2 : (s_nb ? 1 : 0);
}

// ------------------------- gather first 8 tokens ----------------------------
__global__ void gather_x8_kernel(const float* __restrict__ x) {
    int row = blockIdx.x;                        // (b*8 + r)
    int b = row >> 3, r = row & 7;
    const float* src = x + ((size_t)b * NTOK + r) * DIMC;
    float* dst = g_x8 + (size_t)row * DIMC;
    for (int c = threadIdx.x; c < DIMC; c += blockDim.x) dst[c] = src[c];
}

// ------------------------- small NT GEMM with split-K (fp32) ----------------
// C_part[ks][64, DIMC] = A[64, Kslice] * B[DIMC, Kslice]^T  for this K split
// Padding 33: compute-loop Bs bank stride 132 % 32 == 4 -> worst 2-way
// (36 gave 144 % 32 == 16 -> 8-way).
__global__ __launch_bounds__(256)
void small_nt_kernel(const float* __restrict__ A, const float* __restrict__ B,
                     float* __restrict__ Cpart) {
    int n0 = blockIdx.x * 64;
    int ks = blockIdx.y;
    int kbase = ks * 256;
    __shared__ float As[64 * 33];
    __shared__ float Bs[64 * 33];
    int tid = threadIdx.x;
    int tx = tid & 15, ty = tid >> 4;
    float acc[4][4];
#pragma unroll
    for (int i = 0; i < 4; i++)
#pragma unroll
        for (int j = 0; j < 4; j++) acc[i][j] = 0.f;

    for (int kt = 0; kt < 8; kt++) {
        int kb = kbase + kt * 32;
        __syncthreads();
#pragma unroll
        for (int j = 0; j < 2; j++) {
            int idx = tid + 256 * j;
            int m = idx >> 3, k4 = (idx & 7) * 4;
            float4 va = *(const float4*)&A[(size_t)m * DIMC + kb + k4];
            As[m * 33 + k4 + 0] = va.x; As[m * 33 + k4 + 1] = va.y;
            As[m * 33 + k4 + 2] = va.z; As[m * 33 + k4 + 3] = va.w;
            float4 vb = *(const float4*)&B[(size_t)(n0 + m) * DIMC + kb + k4];
            Bs[m * 33 + k4 + 0] = vb.x; Bs[m * 33 + k4 + 1] = vb.y;
            Bs[m * 33 + k4 + 2] = vb.z; Bs[m * 33 + k4 + 3] = vb.w;
        }
        __syncthreads();
#pragma unroll
        for (int k = 0; k < 32; k++) {
            float a[4], bb[4];
#pragma unroll
            for (int i = 0; i < 4; i++) a[i]  = As[(ty * 4 + i) * 33 + k];
#pragma unroll
            for (int j = 0; j < 4; j++) bb[j] = Bs[(tx * 4 + j) * 33 + k];
#pragma unroll
            for (int i = 0; i < 4; i++)
#pragma unroll
                for (int j = 0; j < 4; j++) acc[i][j] += a[i] * bb[j];
        }
    }
#pragma unroll
    for (int i = 0; i < 4; i++)
#pragma unroll
        for (int j = 0; j < 4; j++)
            Cpart[(size_t)ks * 64 * DIMC + (ty * 4 + i) * DIMC + n0 + tx * 4 + j] = acc[i][j];
}

__global__ void reduce_q_kernel() {
    int i = blockIdx.x * 256 + threadIdx.x;
    if (i < 64 * DIMC) {
        float s = 0.f;
#pragma unroll
        for (int ks = 0; ks < 6; ks++) s += g_part[(size_t)ks * 64 * DIMC + i];
        g_q[i] = s * SCALE;
    }
}

__global__ void reduce_out_kernel(const float* __restrict__ bp, float* __restrict__ out) {
    int i = blockIdx.x * 256 + threadIdx.x;
    if (i < 64 * DIMC) {
        float s = bp[i % DIMC];
#pragma unroll
        for (int ks = 0; ks < 6; ks++) s += g_part[(size_t)ks * 64 * DIMC + i];
        out[i] = s;
    }
}

// ------------------------- qk = q @ Wk per head -----------------------------
__global__ __launch_bounds__(128)
void qk_kernel(const float* __restrict__ Wk) {
    int b = blockIdx.z, h = blockIdx.y;
    int c = blockIdx.x * 128 + threadIdx.x;
    __shared__ float qs[8][64];
    for (int idx = threadIdx.x; idx < 512; idx += 128) {
        int r = idx >> 6, d = idx & 63;
        qs[r][d] = g_q[(size_t)(b * 8 + r) * DIMC + h * HD + d];
    }
    __syncthreads();
    float acc[8];
#pragma unroll
    for (int r = 0; r < 8; r++) acc[r] = 0.f;
    for (int d = 0; d < 64; d++) {
        float w = Wk[(size_t)(h * HD + d) * DIMC + c];
#pragma unroll
        for (int r = 0; r < 8; r++) acc[r] += qs[r][d] * w;
    }
#pragma unroll
    for (int r = 0; r < 8; r++)
        g_qk[(size_t)(b * NG + h * 8 + r) * DIMC + c] = acc[r];
}

// ------------------------- logits: C[192,4096] = qk * x^T (NT, tf32) --------
__global__ __launch_bounds__(256)
void gemm_logits_kernel(const float* __restrict__ x) {
    int b = blockIdx.z;
    const float* A = g_qk + (size_t)b * NG * DIMC;
    const float* B = x + (size_t)b * NTOK * DIMC;
    float* C = g_p + (size_t)b * NG * NTOK;
    int m0 = blockIdx.y * 64, n0 = blockIdx.x * 128;
    __shared__ uint32_t As[64 * 36];
    __shared__ uint32_t Bs[128 * 36];
    int tid = threadIdx.x, lane = tid & 31, warp = tid >> 5;
    int wm = warp >> 2, wn = warp & 3;
    int g = lane >> 2, t = lane & 3;
    float acc[2][4][4];
#pragma unroll
    for (int mi = 0; mi < 2; mi++)
#pragma unroll
        for (int ni = 0; ni < 4; ni++)
#pragma unroll
            for (int q = 0; q < 4; q++) acc[mi][ni][q] = 0.f;

    float4 ra[2], rb[4];
    const int KT = DIMC / 32;   // 48
    // prefetch kt=0
#pragma unroll
    for (int j = 0; j < 2; j++) {
        int idx = tid + 256 * j; int am = idx >> 3, ak = (idx & 7) * 4;
        ra[j] = *(const float4*)&A[(size_t)(m0 + am) * DIMC + ak];
    }
#pragma unroll
    for (int j = 0; j < 4; j++) {
        int idx = tid + 256 * j; int bn = idx >> 3, bk = (idx & 7) * 4;
        rb[j] = *(const float4*)&B[(size_t)(n0 + bn) * DIMC + bk];
    }

    for (int kt = 0; kt < KT; kt++) {
        __syncthreads();
#pragma unroll
        for (int j = 0; j < 2; j++) {
            int idx = tid + 256 * j; int am = idx >> 3, ak = (idx & 7) * 4;
            uint32_t* s = &As[am * 36 + ak];
            s[0] = f2tf32(ra[j].x); s[1] = f2tf32(ra[j].y);
            s[2] = f2tf32(ra[j].z); s[3] = f2tf32(ra[j].w);
        }
#pragma unroll
        for (int j = 0; j < 4; j++) {
            int idx = tid + 256 * j; int bn = idx >> 3, bk = (idx & 7) * 4;
            uint32_t* s = &Bs[bn * 36 + bk];
            s[0] = f2tf32(rb[j].x); s[1] = f2tf32(rb[j].y);
            s[2] = f2tf32(rb[j].z); s[3] = f2tf32(rb[j].w);
        }
        __syncthreads();
        if (kt + 1 < KT) {
            int ko = (kt + 1) * 32;
#pragma unroll
            for (int j = 0; j < 2; j++) {
                int idx = tid + 256 * j; int am = idx >> 3, ak = (idx & 7) * 4;
                ra[j] = *(const float4*)&A[(size_t)(m0 + am) * DIMC + ko + ak];
            }
#pragma unroll
            for (int j = 0; j < 4; j++) {
                int idx = tid + 256 * j; int bn = idx >> 3, bk = (idx & 7) * 4;
                rb[j] = *(const float4*)&B[(size_t)(n0 + bn) * DIMC + ko + bk];
            }
        }
#pragma unroll
        for (int kk = 0; kk < 4; kk++) {
            uint32_t af[2][4];
#pragma unroll
            for (int mi = 0; mi < 2; mi++) {
                int base = (wm * 32 + mi * 16 + g) * 36 + kk * 8;
                af[mi][0] = As[base + t];
                af[mi][1] = As[base + 8 * 36 + t];
                af[mi][2] = As[base + t + 4];
                af[mi][3] = As[base + 8 * 36 + t + 4];
            }
#pragma unroll
            for (int ni = 0; ni < 4; ni++) {
                int bb = (wn * 32 + ni * 8 + g) * 36 + kk * 8;
                uint32_t bf[2] = { Bs[bb + t], Bs[bb + t + 4] };
                mma_tf32(acc[0][ni], af[0], bf);
                mma_tf32(acc[1][ni], af[1], bf);
            }
        }
    }
#pragma unroll
    for (int mi = 0; mi < 2; mi++)
#pragma unroll
        for (int ni = 0; ni < 4; ni++) {
            int row = m0 + wm * 32 + mi * 16 + g;
            int col = n0 + wn * 32 + ni * 8 + 2 * t;
            float2 v0 = make_float2(acc[mi][ni][0], acc[mi][ni][1]);
            float2 v1 = make_float2(acc[mi][ni][2], acc[mi][ni][3]);
            *(float2*)&C[(size_t)row * NTOK + col] = v0;
            *(float2*)&C[(size_t)(row + 8) * NTOK + col] = v1;
        }
}

// ------------------------- masked softmax over n ----------------------------
__global__ __launch_bounds__(256)
void softmax_kernel(const void* __restrict__ mask) {
    int b = blockIdx.y, gg = blockIdx.x;
    int r = gg & 7;
    float* row = g_p + (size_t)(b * NG + gg) * NTOK;
    int tid = threadIdx.x, lane = tid & 31, warp = tid >> 5;
    int mode = g_maskmode;
    __shared__ float s1[8], s2[8];

    float vals[16];
    float mx = -1e30f;
#pragma unroll
    for (int j = 0; j < 16; j++) {
        int n = j * 256 + tid;
        float v = row[n];
        bool keep;
        if (n < RR) {
            keep = (n == r);
        } else {
            int mi = (b * RR + r) * MASKW + (n - RR);
            if (mode == 0)      keep = ((const int*)mask)[mi] != 0;
            else if (mode == 1) keep = ((const unsigned char*)mask)[mi] != 0;
            else                keep = ((const float*)mask)[mi] != 0.f;
        }
        v = keep ? v : -1e30f;
        vals[j] = v;
        mx = fmaxf(mx, v);
    }
#pragma unroll
    for (int o = 16; o > 0; o >>= 1) mx = fmaxf(mx, __shfl_xor_sync(0xffffffffu, mx, o));
    if (lane == 0) s1[warp] = mx;
    __syncthreads();
    mx = s1[0];
#pragma unroll
    for (int w = 1; w < 8; w++) mx = fmaxf(mx, s1[w]);

    float sum = 0.f;
#pragma unroll
    for (int j = 0; j < 16; j++) {
        float e = expf(vals[j] - mx);
        vals[j] = e;
        sum += e;
    }
#pragma unroll
    for (int o = 16; o > 0; o >>= 1) sum += __shfl_xor_sync(0xffffffffu, sum, o);
    if (lane == 0) s2[warp] = sum;
    __syncthreads();
    sum = 0.f;
#pragma unroll
    for (int w = 0; w < 8; w++) sum += s2[w];
    float inv = 1.f / sum;
#pragma unroll
    for (int j = 0; j < 16; j++) row[j * 256 + tid] = vals[j] * inv;
}

// ------------------------- y: C[192,1536] = p * x (NN, tf32) ----------------
__global__ __launch_bounds__(256)
void gemm_y_kernel(const float* __restrict__ x) {
    int b = blockIdx.z;
    const float* A = g_p + (size_t)b * NG * NTOK;       // [192,4096] k-contig
    const float* B = x + (size_t)b * NTOK * DIMC;       // [4096,1536] rows=k
    float* C = g_y + (size_t)b * NG * DIMC;
    int m0 = blockIdx.y * 64, c0 = blockIdx.x * 128;
    __shared__ uint32_t As[64 * 36];
    __shared__ uint32_t Bs[32 * 136];
    int tid = threadIdx.x, lane = tid & 31, warp = tid >> 5;
    int wm = warp >> 2, wn = warp & 3;
    int g = lane >> 2, t = lane & 3;
    float acc[2][4][4];
#pragma unroll
    for (int mi = 0; mi < 2; mi++)
#pragma unroll
        for (int ni = 0; ni < 4; ni++)
#pragma unroll
            for (int q = 0; q < 4; q++) acc[mi][ni][q] = 0.f;

    float4 ra[2], rb[4];
    const int KT = NTOK / 32;   // 128
#pragma unroll
    for (int j = 0; j < 2; j++) {
        int idx = tid + 256 * j; int am = idx >> 3, ak = (idx & 7) * 4;
        ra[j] = *(const float4*)&A[(size_t)(m0 + am) * NTOK + ak];
    }
#pragma unroll
    for (int j = 0; j < 4; j++) {
        int idx = tid + 256 * j; int bk = idx >> 5, bc = (idx & 31) * 4;
        rb[j] = *(const float4*)&B[(size_t)bk * DIMC + c0 + bc];
    }

    for (int kt = 0; kt < KT; kt++) {
        __syncthreads();
#pragma unroll
        for (int j = 0; j < 2; j++) {
            int idx = tid + 256 * j; int am = idx >> 3, ak = (idx & 7) * 4;
            uint32_t* s = &As[am * 36 + ak];
            s[0] = f2tf32(ra[j].x); s[1] = f2tf32(ra[j].y);
            s[2] = f2tf32(ra[j].z); s[3] = f2tf32(ra[j].w);
        }
#pragma unroll
        for (int j = 0; j < 4; j++) {
            int idx = tid + 256 * j; int bk = idx >> 5, bc = (idx & 31) * 4;
            uint32_t* s = &Bs[bk * 136 + bc];
            s[0] = f2tf32(rb[j].x); s[1] = f2tf32(rb[j].y);
            s[2] = f2tf32(rb[j].z); s[3] = f2tf32(rb[j].w);
        }
        __syncthreads();
        if (kt + 1 < KT) {
            int ko = (kt + 1) * 32;
#pragma unroll
            for (int j = 0; j < 2; j++) {
                int idx = tid + 256 * j; int am = idx >> 3, ak = (idx & 7) * 4;
                ra[j] = *(const float4*)&A[(size_t)(m0 + am) * NTOK + ko + ak];
            }
#pragma unroll
            for (int j = 0; j < 4; j++) {
                int idx = tid + 256 * j; int bk = idx >> 5, bc = (idx & 31) * 4;
                rb[j] = *(const float4*)&B[(size_t)(ko + bk) * DIMC + c0 + bc];
            }
        }
#pragma unroll
        for (int kk = 0; kk < 4; kk++) {
            uint32_t af[2][4];
#pragma unroll
            for (int mi = 0; mi < 2; mi++) {
                int base = (wm * 32 + mi * 16 + g) * 36 + kk * 8;
                af[mi][0] = As[base + t];
                af[mi][1] = As[base + 8 * 36 + t];
                af[mi][2] = As[base + t + 4];
                af[mi][3] = As[base + 8 * 36 + t + 4];
            }
#pragma unroll
            for (int ni = 0; ni < 4; ni++) {
                int bb = (kk * 8 + t) * 136 + wn * 32 + ni * 8 + g;
                uint32_t bf[2] = { Bs[bb], Bs[bb + 4 * 136] };
                mma_tf32(acc[0][ni], af[0], bf);
                mma_tf32(acc[1][ni], af[1], bf);
            }
        }
    }
#pragma unroll
    for (int mi = 0; mi < 2; mi++)
#pragma unroll
        for (int ni = 0; ni < 4; ni++) {
            int row = m0 + wm * 32 + mi * 16 + g;
            int col = c0 + wn * 32 + ni * 8 + 2 * t;
            float2 v0 = make_float2(acc[mi][ni][0], acc[mi][ni][1]);
            float2 v1 = make_float2(acc[mi][ni][2], acc[mi][ni][3]);
            *(float2*)&C[(size_t)row * DIMC + col] = v0;
            *(float2*)&C[(size_t)(row + 8) * DIMC + col] = v1;
        }
}

// ------------------------- xcls: per-head Wv projection of y ----------------
__global__ __launch_bounds__(256)
void xcls_kernel(const float* __restrict__ Wv) {
    int h = blockIdx.x, b = blockIdx.y;
    __shared__ float ys[8][64];
    __shared__ float wvs[64][65];
    int tid = threadIdx.x;
    int r = tid >> 5, lane = tid & 31;
    int d0 = lane * 2;
    float a0 = 0.f, a1 = 0.f;
    for (int c0 = 0; c0 < DIMC; c0 += 64) {
        __syncthreads();
        for (int idx = tid; idx < 512; idx += 256) {
            int rr = idx >> 6, cc = idx & 63;
            ys[rr][cc] = g_y[(size_t)(b * NG + h * 8 + rr) * DIMC + c0 + cc];
        }
        for (int idx = tid; idx < 4096; idx += 256) {
            int dd = idx >> 6, cc = idx & 63;
            wvs[dd][cc] = Wv[(size_t)(h * HD + dd) * DIMC + c0 + cc];
        }
        __syncthreads();
#pragma unroll
        for (int cc = 0; cc < 64; cc++) {
            float yv = ys[r][cc];
            a0 += yv * wvs[d0][cc];
            a1 += yv * wvs[d0 + 1][cc];
        }
    }
    g_xcls[(size_t)(b * 8 + r) * DIMC + h * HD + d0]     = a0;
    g_xcls[(size_t)(b * 8 + r) * DIMC + h * HD + d0 + 1] = a1;
}

// ---------------------------------------------------------------------------
extern "C" void kernel_launch(void* const* d_in, const int* in_sizes, int n_in,
                              void* d_out, int out_size) {
    const float* x    = (const float*)d_in[0];
    const void*  mask = d_in[1];
    const float* Wq   = (const float*)d_in[2];
    const float* Wk   = (const float*)d_in[3];
    const float* Wv   = (const float*)d_in[4];
    const float* Wp   = (const float*)d_in[5];
    const float* bp   = (const float*)d_in[6];
    float* out = (float*)d_out;

    float* d_x8;   cudaGetSymbolAddress((void**)&d_x8,   g_x8);
    float* d_part; cudaGetSymbolAddress((void**)&d_part, g_part);
    float* d_xcls; cudaGetSymbolAddress((void**)&d_xcls, g_xcls);

    detect_mask_kernel<<<1, 128>>>((const unsigned int*)mask);
    gather_x8_kernel<<<64, 256>>>(x);

    // q partials: x8 @ Wq^T (split-K 6), then reduce*SCALE
    small_nt_kernel<<<dim3(24, 6), 256>>>(d_x8, Wq, d_part);
    reduce_q_kernel<<<384, 256>>>();

    // qk per head
    qk_kernel<<<dim3(12, NH, NB), 128>>>(Wk);

    // logits (tf32 MMA), softmax, y (tf32 MMA)
    gemm_logits_kernel<<<dim3(32, 3, NB), 256>>>(x);
    softmax_kernel<<<dim3(NG, NB), 256>>>(mask);
    gemm_y_kernel<<<dim3(12, 3, NB), 256>>>(x);

    // per-head Wv projection, then output projection + bias
    xcls_kernel<<<dim3(NH, NB), 256>>>(Wv);
    small_nt_kernel<<<dim3(24, 6), 256>>>(d_xcls, Wp, d_part);
    reduce_out_kernel<<<384, 256>>>(bp, out);
}